// round 12
// baseline (speedup 1.0000x reference)
#include <cuda_runtime.h>
#include <math.h>

#define BB 16
#define CIN 3
#define HIDC 64
#define SS 16384
#define QQ 4096               // SS/4
#define MM 16
#define LL 4
#define NPSP 500
#define NPFR 200
#define EDIM 8
#define NHEADS 4
#define CHPH 16               // channels per head
#define NDCH 64               // DFT chunks
#define NIDXC 8               // idx-kernel chunks

// ---------------- scratch (device globals; no allocation) ----------------
__device__ float d_mT[QQ * 2 * MM];                      // (cos,sin) pairs per (q, m)
__device__ float d_h[BB * SS * HIDC];                    // activation, [b][s][d]
__device__ float d_sC[BB * SS];                          // channel-sum of h
__device__ int   d_idx[BB * SS];                         // spatial hash indices
__device__ float d_Xpart[BB * HIDC * NDCH * 32];         // DFT partials (8.4 MB)
__device__ float d_esum[BB * NIDXC * EDIM];              // partial emb sums
__device__ float d_cA[BB * HIDC * MM];                   // fused cos coefficients
__device__ float d_cB[BB * HIDC * MM];                   // fused sin coefficients
__device__ float d_spw2[BB * HIDC * EDIM];               // gate-folded spatial W
__device__ float d_spb2[BB * HIDC];                      // gate-folded spatial b
__device__ float d_spT[BB * NPSP * HIDC];                // per-pattern sp+DC table

__device__ __forceinline__ float gelu_exact(float v) {
    return 0.5f * v * (1.0f + erff(v * 0.70710678118654752f));
}
__device__ __forceinline__ unsigned long long pk2(float lo, float hi) {
    unsigned long long r;
    asm("mov.b64 %0, {%1, %2};" : "=l"(r) : "f"(lo), "f"(hi));
    return r;
}
__device__ __forceinline__ void upk2(float& lo, float& hi, unsigned long long v) {
    asm("mov.b64 {%0, %1}, %2;" : "=f"(lo), "=f"(hi) : "l"(v));
}
__device__ __forceinline__ void fma2(unsigned long long& d, unsigned long long a, unsigned long long b) {
    asm("fma.rn.f32x2 %0, %1, %2, %0;" : "+l"(d) : "l"(a), "l"(b));
}
__device__ __forceinline__ void add2(unsigned long long& d, unsigned long long a) {
    asm("add.rn.f32x2 %0, %0, %1;" : "+l"(d) : "l"(a));
}

// ---------------- trig table: d_mT[q*32 + m*2] = cos(2pi q m/S), +1 = sin ---------
__global__ void k_table() {
    int i = blockIdx.x * blockDim.x + threadIdx.x;   // < QQ*MM
    int q = i >> 4, m = i & 15;
    int r = (q * m) & (SS - 1);
    double a = 6.283185307179586476925286766559 * (double)r / (double)SS;
    d_mT[q * 32 + m * 2]     = (float)cos(a);
    d_mT[q * 32 + m * 2 + 1] = (float)sin(a);
}

// ---------------- lifting: x[B,3,S] -> h[b][s][d], plus channel-sum ----------------
__global__ __launch_bounds__(256) void k_lift(const float* __restrict__ x,
                                              const float* __restrict__ W,
                                              const float* __restrict__ bv) {
    __shared__ float sW[CIN * HIDC];
    __shared__ float sB[HIDC];
    int t = threadIdx.x;
    if (t < CIN * HIDC) sW[t] = W[t];
    if (t < HIDC) sB[t] = bv[t];
    __syncthreads();
    int b = blockIdx.x;
    int s = blockIdx.y * 256 + t;
    float x0 = x[(b * CIN + 0) * SS + s];
    float x1 = x[(b * CIN + 1) * SS + s];
    float x2 = x[(b * CIN + 2) * SS + s];
    float sc = 0.f;
    float4* hp = (float4*)(d_h + ((size_t)b * SS + s) * HIDC);
#pragma unroll
    for (int j = 0; j < HIDC / 4; j++) {
        float4 v;
        float* vv = (float*)&v;
#pragma unroll
        for (int u = 0; u < 4; u++) {
            int d = j * 4 + u;
            float w = sB[d];
            w = fmaf(x0, sW[0 * HIDC + d], w);
            w = fmaf(x1, sW[1 * HIDC + d], w);
            w = fmaf(x2, sW[2 * HIDC + d], w);
            vv[u] = w; sc += w;
        }
        hp[j] = v;
    }
    d_sC[b * SS + s] = sc;
}

// ---------------- spatial hash indices + embedding mean partials ----------------
__global__ __launch_bounds__(256) void k_idx(const float* __restrict__ spEmb) {
    int b = blockIdx.x;
    int chunk = blockIdx.y;
    int t = threadIdx.x;
    const float* sc = d_sC + b * SS;
    float es[EDIM];
#pragma unroll
    for (int k = 0; k < EDIM; k++) es[k] = 0.f;
    const int span = SS / NIDXC;        // 2048
    for (int it = 0; it < span / 256; it++) {
        int s = chunk * span + it * 256 + t;
        int sm2 = max(s - 2, 0), sm1 = max(s - 1, 0), sp1 = min(s + 1, SS - 1);
        float w = sc[sm2] + sc[sm1] + sc[s] + sc[sp1];
        int iv = (int)(w * 31.0f);      // trunc toward zero
        iv %= NPSP; if (iv < 0) iv += NPSP;
        d_idx[b * SS + s] = iv;
        const float* e = spEmb + iv * EDIM;
#pragma unroll
        for (int k = 0; k < EDIM; k++) es[k] += __ldg(e + k);
    }
    __shared__ float red[256][EDIM];
#pragma unroll
    for (int k = 0; k < EDIM; k++) red[t][k] = es[k];
    __syncthreads();
    for (int off = 128; off > 0; off >>= 1) {
        if (t < off) {
#pragma unroll
            for (int k = 0; k < EDIM; k++) red[t][k] += red[t + off][k];
        }
        __syncthreads();
    }
    if (t < EDIM) d_esum[(b * NIDXC + chunk) * EDIM + t] = red[0][t];
}

// ---------------- 16-mode DFT: thread-per-channel, packed f32x2, quartet fold ----
// acc[m] = (R_m, +sum h*sin) packed. I negated later in k_coeff.
__global__ __launch_bounds__(256) void k_dft() {
    __shared__ float sred[4][HIDC][33];   // padded: conflict-free
    int b = blockIdx.x, chunk = blockIdx.y;        // chunk 0..63
    int t = threadIdx.x, d = t & 63, strand = t >> 6;
    const float* hb = d_h + (size_t)b * SS * HIDC + d;
    unsigned long long acc[MM];
#pragma unroll
    for (int m = 0; m < MM; m++) acc[m] = 0ULL;
#pragma unroll 2
    for (int i = 0; i < 16; i++) {
        int q = chunk * 64 + strand * 16 + i;
        if (q == 0) {
            // degenerate positions {0, 4096, 8192, 12288}, exact trig
            float u = hb[0];
            float w = hb[(size_t)4096 * HIDC];
            float v = hb[(size_t)8192 * HIDC];
            float z = hb[(size_t)12288 * HIDC];
            float wzp = w + z, wzm = w - z;
#pragma unroll
            for (int m = 0; m < MM; m++) {
                float rA = u + ((m & 1) ? -v : v);
                float iA = 0.f;
                int mm = m & 3;
                if (mm == 0)      rA += wzp;
                else if (mm == 2) rA -= wzp;
                else if (mm == 1) iA += wzm;
                else              iA -= wzm;
                add2(acc[m], pk2(rA, iA));
            }
            continue;
        }
        float ha  = hb[(size_t)q * HIDC];
        float hbv = hb[(size_t)(8192 - q) * HIDC];
        float hc  = hb[(size_t)(8192 + q) * HIDC];
        float he  = hb[(size_t)(16384 - q) * HIDC];
        float p = ha + he, qv = hbv + hc, r = ha - he, tv = hc - hbv;
        unsigned long long xye = pk2(p + qv, r + tv);
        unsigned long long xyo = pk2(p - qv, r - tv);
        const ulonglong2* tp = (const ulonglong2*)(d_mT + q * 32);
        ulonglong2 w0 = tp[0], w1 = tp[1], w2 = tp[2], w3 = tp[3];
        fma2(acc[0], w0.x, xye); fma2(acc[1], w0.y, xyo);
        fma2(acc[2], w1.x, xye); fma2(acc[3], w1.y, xyo);
        fma2(acc[4], w2.x, xye); fma2(acc[5], w2.y, xyo);
        fma2(acc[6], w3.x, xye); fma2(acc[7], w3.y, xyo);
        ulonglong2 w4 = tp[4], w5 = tp[5], w6 = tp[6], w7 = tp[7];
        fma2(acc[8],  w4.x, xye); fma2(acc[9],  w4.y, xyo);
        fma2(acc[10], w5.x, xye); fma2(acc[11], w5.y, xyo);
        fma2(acc[12], w6.x, xye); fma2(acc[13], w6.y, xyo);
        fma2(acc[14], w7.x, xye); fma2(acc[15], w7.y, xyo);
    }
#pragma unroll
    for (int m = 0; m < MM; m++) {
        float lo, hi; upk2(lo, hi, acc[m]);
        sred[strand][d][2 * m] = lo;
        sred[strand][d][2 * m + 1] = hi;
    }
    __syncthreads();
#pragma unroll
    for (int k = 0; k < 8; k++) {
        int item = t * 8 + k;             // 0..2047
        int c = item >> 5, j = item & 31;
        float s = sred[0][c][j] + sred[1][c][j] + sred[2][c][j] + sred[3][c][j];
        d_Xpart[((size_t)(b * HIDC + c) * NDCH + chunk) * 32 + j] = s;
    }
}

// ---------------- per-batch: reduce X, mh mixing, fr hash, gating, coefficients ----------------
__global__ __launch_bounds__(256) void k_coeff(int layer,
        const float* __restrict__ frEmb, const float* __restrict__ frW, const float* __restrict__ frB,
        const float* __restrict__ spW, const float* __restrict__ spB,
        const float* __restrict__ gW1, const float* __restrict__ gB1,
        const float* __restrict__ gW2, const float* __restrict__ gB2,
        const float* __restrict__ Wr, const float* __restrict__ Wi) {
    int b = blockIdx.x, t = threadIdx.x;
    __shared__ float sXr[HIDC][MM], sXi[HIDC][MM];
    __shared__ float sOr[HIDC][MM], sOi[HIDC][MM];
    __shared__ float sP[HIDC][MM];
    __shared__ int   smagi[MM];
    __shared__ int   sIdxFr;
    __shared__ float sEbar[EDIM];
    __shared__ float sg[3 * HIDC];
    __shared__ float sh1[HIDC];
    __shared__ float swv[3];

    // A: reduce DFT partials (fixed order), negate imag to true sign
    for (int jg = t; jg < HIDC * 32; jg += 256) {
        int c = jg >> 5, j = jg & 31;
        const float* p = d_Xpart + ((size_t)(b * HIDC + c) * NDCH) * 32 + j;
        float s = 0.f;
#pragma unroll 8
        for (int chunk = 0; chunk < NDCH; chunk++) s += p[chunk * 32];
        int m = j >> 1;
        if (j & 1) sXi[c][m] = -s; else sXr[c][m] = s;
    }
    __syncthreads();
    // B: spectral hash
    if (t < MM) {
        float acc = 0.f;
        for (int c = 0; c < HIDC; c++) {
            float xr = sXr[c][t], xi = sXi[c][t];
            acc += sqrtf(xr * xr + xi * xi);
        }
        float mag = acc * (1.0f / 64.0f);
        smagi[t] = (int)(mag * 1000.0f);
    }
    __syncthreads();
    if (t == 0) {
        int tot = 0;
#pragma unroll
        for (int m = 0; m < MM; m++) tot += smagi[m];
        tot %= NPFR; if (tot < 0) tot += NPFR;
        sIdxFr = tot;
    }
    if (t >= 32 && t < 32 + EDIM) {
        int k = t - 32; float s = 0.f;
        for (int p = 0; p < NIDXC; p++) s += d_esum[(b * NIDXC + p) * EDIM + k];
        sEbar[k] = s * (1.0f / (float)SS);
    }
    __syncthreads();
    // C: fr projection P[c][m]
    {
        float ef[EDIM];
        const float* er = frEmb + (layer * NPFR + sIdxFr) * EDIM;
#pragma unroll
        for (int k = 0; k < EDIM; k++) ef[k] = __ldg(er + k);
        for (int o = t; o < HIDC * MM; o += 256) {
            float v = frB[layer * HIDC * MM + o];
#pragma unroll
            for (int k = 0; k < EDIM; k++)
                v = fmaf(ef[k], frW[(layer * EDIM + k) * HIDC * MM + o], v);
            sP[o >> 4][o & 15] = v;
        }
    }
    // D: complex head mixing O = X W  (W[L][H][i][o][m])
    for (int q = t; q < HIDC * MM; q += 256) {
        int hh = q >> 8;
        int o = (q >> 4) & 15;
        int m = q & 15;
        float ar = 0.f, ai = 0.f;
        const float* wr = Wr + (((size_t)(layer * NHEADS + hh) * CHPH) * CHPH + o) * MM + m;
        const float* wi = Wi + (((size_t)(layer * NHEADS + hh) * CHPH) * CHPH + o) * MM + m;
#pragma unroll
        for (int i = 0; i < CHPH; i++) {
            float xr = sXr[hh * CHPH + i][m], xi = sXi[hh * CHPH + i][m];
            float wrv = wr[i * CHPH * MM], wiv = wi[i * CHPH * MM];
            ar = fmaf(xr, wrv, ar); ar = fmaf(-xi, wiv, ar);
            ai = fmaf(xr, wiv, ai); ai = fmaf(xi, wrv, ai);
        }
        sOr[hh * CHPH + o][m] = ar;
        sOi[hh * CHPH + o][m] = ai;
    }
    __syncthreads();
    // E: gating (analytic branch means)
    if (t < 3 * HIDC) {
        float v;
        if (t < HIDC) {
            v = spB[layer * HIDC + t];
#pragma unroll
            for (int k = 0; k < EDIM; k++)
                v = fmaf(sEbar[k], spW[(layer * EDIM + k) * HIDC + t], v);
        } else if (t < 2 * HIDC) {
            v = sOr[t - HIDC][0] * (1.0f / (float)SS);
        } else {
            v = sP[t - 2 * HIDC][0] * (1.0f / (float)SS);
        }
        sg[t] = v;
    }
    __syncthreads();
    if (t < HIDC) {
        float v = gB1[layer * 64 + t];
        for (int k = 0; k < 3 * HIDC; k++)
            v = fmaf(sg[k], gW1[(layer * 3 * HIDC + k) * 64 + t], v);
        sh1[t] = fmaxf(v, 0.f);
    }
    __syncthreads();
    if (t < 3) {
        float v = gB2[layer * 3 + t];
        for (int k = 0; k < HIDC; k++)
            v = fmaf(sh1[k], gW2[(layer * HIDC + k) * 3 + t], v);
        swv[t] = v;
    }
    __syncthreads();
    if (t == 0) {
        float mx = fmaxf(swv[0], fmaxf(swv[1], swv[2]));
        float e0 = expf(swv[0] - mx), e1 = expf(swv[1] - mx), e2 = expf(swv[2] - mx);
        float inv = 1.f / (e0 + e1 + e2);
        swv[0] = e0 * inv; swv[1] = e1 * inv; swv[2] = e2 * inv;
    }
    __syncthreads();
    // F: gate-folded synthesis coefficients
    if (t < HIDC) {
        int d = t;
        float w0 = swv[0], w1 = swv[1], w2 = swv[2];
        const float invS = 1.0f / (float)SS;
        float* A = d_cA + (b * HIDC + d) * MM;
        float* Bc = d_cB + (b * HIDC + d) * MM;
        A[0] = invS * (w1 * sOr[d][0] + w2 * sP[d][0]);
        Bc[0] = 0.f;
#pragma unroll
        for (int m = 1; m < MM; m++) {
            A[m] = 2.f * invS * (w1 * sOr[d][m] + w2 * sP[d][m]);
            Bc[m] = -2.f * invS * w1 * sOi[d][m];
        }
#pragma unroll
        for (int k = 0; k < EDIM; k++)
            d_spw2[(b * HIDC + d) * EDIM + k] = w0 * spW[(layer * EDIM + k) * HIDC + d];
        d_spb2[b * HIDC + d] = w0 * spB[layer * HIDC + d];
    }
}

// ---------------- per-layer spatial+DC table: T[b][p][d] = spb2 + A0 + emb[p]@spw2 ----
__global__ __launch_bounds__(256) void k_spt(const float* __restrict__ spEmb) {
    int b = blockIdx.x;
    int t = threadIdx.x;
    int d = t & 63, pl = t >> 6;
    int p = blockIdx.y * 4 + pl;
    float v = d_spb2[b * HIDC + d] + d_cA[(b * HIDC + d) * MM];
#pragma unroll
    for (int k = 0; k < EDIM; k++)
        v = fmaf(__ldg(spEmb + p * EDIM + k), d_spw2[(b * HIDC + d) * EDIM + k], v);
    d_spT[(b * NPSP + p) * HIDC + d] = v;
}

// ---------------- fused synthesis + GELU: thread=(position-in-quartet j, channel d) ---
// Signs baked per-thread into packed coefficients:
//  j=0 (+c,+s), j=1 ((-1)^m c, -(-1)^m s), j=2 ((-1)^m c, +(-1)^m s), j=3 (+c,-s)
__global__ __launch_bounds__(256) void k_fusion(int last,
        const float* __restrict__ pW, const float* __restrict__ pB,
        float* __restrict__ out) {
    __shared__ float sA[HIDC][MM + 1];
    __shared__ float sB[HIDC][MM + 1];
    __shared__ float sCp[16][8];
    __shared__ float sPJv[HIDC];
    int b = blockIdx.x, tile = blockIdx.y, t = threadIdx.x;
    int d = t & 63, j = t >> 6;
    for (int i = t; i < HIDC * MM; i += 256) {
        sA[i >> 4][i & 15] = d_cA[b * HIDC * MM + i];
        sB[i >> 4][i & 15] = d_cB[b * HIDC * MM + i];
    }
    if (t < HIDC) sPJv[t] = last ? pW[t] : 0.f;
    __syncthreads();
    unsigned long long cf[MM];
    cf[0] = 0ULL;
#pragma unroll
    for (int m = 1; m < MM; m++) {
        float a = sA[d][m], bb = sB[d][m];
        float sc, ssn;
        if (j == 0)      { sc = 1.f;  ssn = 1.f; }
        else if (j == 3) { sc = 1.f;  ssn = -1.f; }
        else {
            float pm = (m & 1) ? -1.f : 1.f;
            sc = pm; ssn = (j == 1) ? -pm : pm;
        }
        cf[m] = pk2(a * sc, bb * ssn);
    }
    float pj = sPJv[d];
    const float* Tb = d_spT + b * NPSP * HIDC;
    float* hbase = d_h + (size_t)b * SS * HIDC;
    for (int it = 0; it < 16; it++) {
        int q = tile * 16 + it;
        int pos;
        float g;
        if (q == 0 && j >= 2) {
            // special positions 4096 (j=2) and 12288 (j=3)
            pos = (j == 2) ? 4096 : 12288;
            int iv = d_idx[b * SS + pos];
            float v = Tb[iv * HIDC + d];
            float sgn = (j == 2) ? 1.f : -1.f;
#pragma unroll
            for (int m = 1; m < MM; m++) {
                int mm = m & 3;
                if (mm == 0)      v += sA[d][m];
                else if (mm == 2) v -= sA[d][m];
                else if (mm == 1) v = fmaf(sgn, sB[d][m], v);
                else              v = fmaf(-sgn, sB[d][m], v);
            }
            g = gelu_exact(v);
        } else {
            pos = (j == 0) ? q : (j == 1) ? 8192 - q : (j == 2) ? 8192 + q : 16384 - q;
            int iv = d_idx[b * SS + pos];
            float Tv = Tb[iv * HIDC + d];
            const ulonglong2* tp = (const ulonglong2*)(d_mT + q * 32);
            ulonglong2 w0 = tp[0], w1 = tp[1], w2 = tp[2], w3 = tp[3];
            unsigned long long acc = 0ULL;
            fma2(acc, cf[1], w0.y);
            fma2(acc, cf[2], w1.x); fma2(acc, cf[3], w1.y);
            fma2(acc, cf[4], w2.x); fma2(acc, cf[5], w2.y);
            fma2(acc, cf[6], w3.x); fma2(acc, cf[7], w3.y);
            ulonglong2 w4 = tp[4], w5 = tp[5], w6 = tp[6], w7 = tp[7];
            fma2(acc, cf[8],  w4.x); fma2(acc, cf[9],  w4.y);
            fma2(acc, cf[10], w5.x); fma2(acc, cf[11], w5.y);
            fma2(acc, cf[12], w6.x); fma2(acc, cf[13], w6.y);
            fma2(acc, cf[14], w7.x); fma2(acc, cf[15], w7.y);
            float lo, hi; upk2(lo, hi, acc);
            g = gelu_exact(Tv + lo + hi);
        }
        float contrib;
        if (last) contrib = pj * g;
        else { hbase[(size_t)pos * HIDC + d] = g; contrib = g; }
#pragma unroll
        for (int off = 16; off > 0; off >>= 1)
            contrib += __shfl_down_sync(0xffffffffu, contrib, off);
        if ((t & 31) == 0) sCp[it][t >> 5] = contrib;
    }
    __syncthreads();
    if (t < 64) {
        int it = t >> 2, jj = t & 3;
        int q = tile * 16 + it;
        int pos;
        if (q == 0 && jj >= 2) pos = (jj == 2) ? 4096 : 12288;
        else pos = (jj == 0) ? q : (jj == 1) ? 8192 - q : (jj == 2) ? 8192 + q : 16384 - q;
        float tot = sCp[it][jj * 2] + sCp[it][jj * 2 + 1];
        if (last) out[b * SS + pos] = tot + pB[0];
        else d_sC[b * SS + pos] = tot;
    }
}

extern "C" void kernel_launch(void* const* d_in, const int* in_sizes, int n_in,
                              void* d_out, int out_size) {
    const float* x     = (const float*)d_in[0];
    const float* liftW = (const float*)d_in[1];
    const float* liftB = (const float*)d_in[2];
    const float* projW = (const float*)d_in[3];
    const float* projB = (const float*)d_in[4];
    const float* spEmb = (const float*)d_in[5];
    const float* spW   = (const float*)d_in[6];
    const float* spB   = (const float*)d_in[7];
    const float* frEmb = (const float*)d_in[8];
    const float* frW   = (const float*)d_in[9];
    const float* frB   = (const float*)d_in[10];
    const float* gW1   = (const float*)d_in[11];
    const float* gB1   = (const float*)d_in[12];
    const float* gW2   = (const float*)d_in[13];
    const float* gB2   = (const float*)d_in[14];
    const float* mhWr  = (const float*)d_in[15];
    const float* mhWi  = (const float*)d_in[16];

    k_table<<<QQ * MM / 256, 256>>>();
    k_lift<<<dim3(BB, SS / 256), 256>>>(x, liftW, liftB);
    for (int l = 0; l < LL; l++) {
        k_idx<<<dim3(BB, NIDXC), 256>>>(spEmb + l * NPSP * EDIM);
        k_dft<<<dim3(BB, NDCH), 256>>>();
        k_coeff<<<BB, 256>>>(l, frEmb, frW, frB, spW, spB,
                             gW1, gB1, gW2, gB2, mhWr, mhWi);
        k_spt<<<dim3(BB, NPSP / 4), 256>>>(spEmb + l * NPSP * EDIM);
        k_fusion<<<dim3(BB, QQ / 16), 256>>>((l == LL - 1) ? 1 : 0,
                                             projW, projB, (float*)d_out);
    }
}

// round 13
// speedup vs baseline: 1.0306x; 1.0306x over previous
#include <cuda_runtime.h>
#include <math.h>

#define BB 16
#define CIN 3
#define HIDC 64
#define SS 16384
#define QQ 4096               // SS/4
#define MM 16
#define LL 4
#define NPSP 500
#define NPFR 200
#define EDIM 8
#define NHEADS 4
#define CHPH 16               // channels per head
#define NCHUNK 4              // DFT q-chunks (quarter-range)
#define NPART 64              // partials per channel = NCHUNK*2 halves*8 warps
#define NIDXC 8               // idx-kernel chunks

// ---------------- scratch (device globals; no allocation) ----------------
__device__ float d_tabC[SS];
__device__ float d_tabS[SS];
__device__ float d_tabC7[QQ];                            // cos(7*2*pi*q/S)
__device__ float d_tabS7[QQ];
__device__ float d_tabC8[QQ];                            // cos(8*2*pi*q/S)
__device__ float d_tabS8[QQ];
__device__ float d_h[BB * HIDC * SS];                    // 64 MB activation [b][c][s]
__device__ float d_sC[BB * SS];                          // channel-sum of h
__device__ int   d_idx[BB * SS];                         // spatial hash indices
__device__ float d_Xpart[BB * HIDC * NPART * 16];        // DFT partials (4 MB)
__device__ float d_esum[BB * NIDXC * EDIM];              // partial emb sums
__device__ float d_cA[BB * HIDC * MM];                   // fused cos coefficients
__device__ float d_cB[BB * HIDC * MM];                   // fused sin coefficients
__device__ float d_spw2[BB * HIDC * EDIM];               // gate-folded spatial W
__device__ float d_spb2[BB * HIDC];                      // gate-folded spatial b
__device__ float d_spT[BB * NPSP * HIDC];                // per-pattern sp+DC table

__device__ __forceinline__ float gelu_exact(float v) {
    return 0.5f * v * (1.0f + erff(v * 0.70710678118654752f));
}

// ---------------- trig tables (exact base angles) ----------------
__global__ void k_table() {
    int i = blockIdx.x * blockDim.x + threadIdx.x;
    if (i < SS) {
        double w = 6.283185307179586476925286766559 / (double)SS;
        double a = w * (double)i;
        d_tabC[i] = (float)cos(a);
        d_tabS[i] = (float)sin(a);
        if (i < QQ) {
            d_tabC7[i] = (float)cos(a * 7.0);
            d_tabS7[i] = (float)sin(a * 7.0);
            d_tabC8[i] = (float)cos(a * 8.0);
            d_tabS8[i] = (float)sin(a * 8.0);
        }
    }
}

// ---------------- lifting: x[B,3,S] -> h[B,64,S], plus channel-sum ----------------
__global__ __launch_bounds__(256) void k_lift(const float* __restrict__ x,
                                              const float* __restrict__ W,
                                              const float* __restrict__ bv) {
    __shared__ float sW[CIN * HIDC];
    __shared__ float sB[HIDC];
    int t = threadIdx.x;
    if (t < CIN * HIDC) sW[t] = W[t];
    if (t < HIDC) sB[t] = bv[t];
    __syncthreads();
    int b = blockIdx.x;
    int s = blockIdx.y * 256 + t;
    float x0 = x[(b * CIN + 0) * SS + s];
    float x1 = x[(b * CIN + 1) * SS + s];
    float x2 = x[(b * CIN + 2) * SS + s];
    float sc = 0.f;
#pragma unroll 8
    for (int d = 0; d < HIDC; d++) {
        float v = sB[d];
        v = fmaf(x0, sW[0 * HIDC + d], v);
        v = fmaf(x1, sW[1 * HIDC + d], v);
        v = fmaf(x2, sW[2 * HIDC + d], v);
        d_h[(b * HIDC + d) * SS + s] = v;
        sc += v;
    }
    d_sC[b * SS + s] = sc;
}

// ---------------- spatial hash indices + embedding mean partials ----------------
__global__ __launch_bounds__(256) void k_idx(const float* __restrict__ spEmb) {
    int b = blockIdx.x;
    int chunk = blockIdx.y;
    int t = threadIdx.x;
    const float* sc = d_sC + b * SS;
    float es[EDIM];
#pragma unroll
    for (int k = 0; k < EDIM; k++) es[k] = 0.f;
    const int span = SS / NIDXC;        // 2048
    for (int it = 0; it < span / 256; it++) {
        int s = chunk * span + it * 256 + t;
        int sm2 = max(s - 2, 0), sm1 = max(s - 1, 0), sp1 = min(s + 1, SS - 1);
        float w = sc[sm2] + sc[sm1] + sc[s] + sc[sp1];
        int iv = (int)(w * 31.0f);      // trunc toward zero
        iv %= NPSP; if (iv < 0) iv += NPSP;
        d_idx[b * SS + s] = iv;
        const float* e = spEmb + iv * EDIM;
#pragma unroll
        for (int k = 0; k < EDIM; k++) es[k] += __ldg(e + k);
    }
    __shared__ float red[256][EDIM];
#pragma unroll
    for (int k = 0; k < EDIM; k++) red[t][k] = es[k];
    __syncthreads();
    for (int off = 128; off > 0; off >>= 1) {
        if (t < off) {
#pragma unroll
            for (int k = 0; k < EDIM; k++) red[t][k] += red[t + off][k];
        }
        __syncthreads();
    }
    if (t < EDIM) d_esum[(b * NIDXC + chunk) * EDIM + t] = red[0][t];
}

// ---------------- 16-mode DFT: quartet fold + mode-split (8 modes/block) ---------
// (identical to the measured 529.5us baseline)
__global__ __launch_bounds__(256) void k_dft() {
    int bc = blockIdx.x;            // b*32 + channel-pair
    int b = bc >> 5, cp = bc & 31;
    int cy = blockIdx.y;            // chunk*2 + half
    int chunk = cy >> 1, half = cy & 1;
    const float* h0 = d_h + (size_t)(b * HIDC + cp * 2) * SS;
    const float* h1 = h0 + SS;
    int t = threadIdx.x;
    float aR0[8], aI0[8], aR1[8], aI1[8];
#pragma unroll
    for (int lm = 0; lm < 8; lm++) { aR0[lm] = 0.f; aI0[lm] = 0.f; aR1[lm] = 0.f; aI1[lm] = 0.f; }
#pragma unroll
    for (int it = 0; it < QQ / NCHUNK / 256; it++) {     // 4 iterations
        int q = chunk * (QQ / NCHUNK) + it * 256 + t;
        if (q == 0) {
            float u0 = h0[0], u1 = h1[0];
            float v0 = h0[8192], v1 = h1[8192];
            float w0 = h0[4096], w1 = h1[4096];
            float z0 = h0[12288], z1 = h1[12288];
            float wzp0 = w0 + z0, wzm0 = w0 - z0;
            float wzp1 = w1 + z1, wzm1 = w1 - z1;
#pragma unroll
            for (int lm = 0; lm < 8; lm++) {
                int m = half * 8 + lm;
                aR0[lm] += u0 + ((m & 1) ? -v0 : v0);
                aR1[lm] += u1 + ((m & 1) ? -v1 : v1);
                int mm = m & 3;
                if (mm == 0)      { aR0[lm] += wzp0; aR1[lm] += wzp1; }
                else if (mm == 2) { aR0[lm] -= wzp0; aR1[lm] -= wzp1; }
                else if (mm == 1) { aI0[lm] += wzm0; aI1[lm] += wzm1; }
                else              { aI0[lm] -= wzm0; aI1[lm] -= wzm1; }
            }
            continue;
        }
        float a0 = h0[q], b0v = h0[8192 - q], c0v = h0[8192 + q], e0 = h0[16384 - q];
        float a1 = h1[q], b1v = h1[8192 - q], c1v = h1[8192 + q], e1 = h1[16384 - q];
        float p0 = a0 + e0, q0v = b0v + c0v, r0 = a0 - e0, t0v = c0v - b0v;
        float xe0 = p0 + q0v, xo0 = p0 - q0v, ye0 = r0 + t0v, yo0 = r0 - t0v;
        float p1 = a1 + e1, q1v = b1v + c1v, r1 = a1 - e1, t1v = c1v - b1v;
        float xe1 = p1 + q1v, xo1 = p1 - q1v, ye1 = r1 + t1v, yo1 = r1 - t1v;
        float cb = __ldg(&d_tabC[q]);
        float t2 = cb + cb;
        float cc, sv, cm1, sm1;
        if (half == 0) {
            cc = 1.f; sv = 0.f;
            cm1 = cb; sm1 = -__ldg(&d_tabS[q]);
        } else {
            cc  = __ldg(&d_tabC8[q]); sv  = __ldg(&d_tabS8[q]);
            cm1 = __ldg(&d_tabC7[q]); sm1 = __ldg(&d_tabS7[q]);
        }
#pragma unroll
        for (int lm = 0; lm < 8; lm++) {
            if (lm & 1) {
                aR0[lm] = fmaf(cc, xo0, aR0[lm]); aI0[lm] = fmaf(sv, yo0, aI0[lm]);
                aR1[lm] = fmaf(cc, xo1, aR1[lm]); aI1[lm] = fmaf(sv, yo1, aI1[lm]);
            } else {
                aR0[lm] = fmaf(cc, xe0, aR0[lm]); aI0[lm] = fmaf(sv, ye0, aI0[lm]);
                aR1[lm] = fmaf(cc, xe1, aR1[lm]); aI1[lm] = fmaf(sv, ye1, aI1[lm]);
            }
            float cn = fmaf(t2, cc, -cm1);
            float sn = fmaf(t2, sv, -sm1);
            cm1 = cc; cc = cn; sm1 = sv; sv = sn;
        }
    }
#pragma unroll
    for (int off = 16; off > 0; off >>= 1) {
#pragma unroll
        for (int lm = 0; lm < 8; lm++) {
            aR0[lm] += __shfl_down_sync(0xffffffffu, aR0[lm], off);
            aI0[lm] += __shfl_down_sync(0xffffffffu, aI0[lm], off);
            aR1[lm] += __shfl_down_sync(0xffffffffu, aR1[lm], off);
            aI1[lm] += __shfl_down_sync(0xffffffffu, aI1[lm], off);
        }
    }
    int w = t >> 5, lane = t & 31;
    if (lane == 0) {
        int part = chunk * 16 + half * 8 + w;          // 0..63
        float* o0 = d_Xpart + ((size_t)(b * HIDC + cp * 2) * NPART + part) * 16;
        float* o1 = o0 + (size_t)NPART * 16;
#pragma unroll
        for (int lm = 0; lm < 8; lm++) {
            o0[2 * lm] = aR0[lm]; o0[2 * lm + 1] = aI0[lm];
            o1[2 * lm] = aR1[lm]; o1[2 * lm + 1] = aI1[lm];
        }
    }
}

// ---------------- per-batch: reduce X, mh mixing, fr hash, gating, coefficients ----------------
__global__ __launch_bounds__(256) void k_coeff(int layer,
        const float* __restrict__ frEmb, const float* __restrict__ frW, const float* __restrict__ frB,
        const float* __restrict__ spW, const float* __restrict__ spB,
        const float* __restrict__ gW1, const float* __restrict__ gB1,
        const float* __restrict__ gW2, const float* __restrict__ gB2,
        const float* __restrict__ Wr, const float* __restrict__ Wi) {
    int b = blockIdx.x, t = threadIdx.x;
    __shared__ float sXr[HIDC][MM], sXi[HIDC][MM];
    __shared__ float sOr[HIDC][MM], sOi[HIDC][MM];
    __shared__ float sP[HIDC][MM];
    __shared__ int   smagi[MM];
    __shared__ int   sIdxFr;
    __shared__ float sEbar[EDIM];
    __shared__ float sg[3 * HIDC];
    __shared__ float sh1[HIDC];
    __shared__ float swv[3];

    // A: reduce DFT partials (fixed order), negate imag to true sign.
    for (int jg = t; jg < HIDC * 32; jg += 256) {
        int c = jg >> 5, j = jg & 31;
        int m = j >> 1, ri = j & 1;
        int half = m >> 3, lm = m & 7;
        const float* p = d_Xpart + ((size_t)(b * HIDC + c) * NPART + half * 8) * 16 + lm * 2 + ri;
        float s = 0.f;
#pragma unroll
        for (int chunk = 0; chunk < NCHUNK; chunk++)
#pragma unroll
            for (int w = 0; w < 8; w++)
                s += p[(chunk * 16 + w) * 16];
        if (ri) sXi[c][m] = -s; else sXr[c][m] = s;
    }
    __syncthreads();
    // B: spectral hash
    if (t < MM) {
        float acc = 0.f;
        for (int c = 0; c < HIDC; c++) {
            float xr = sXr[c][t], xi = sXi[c][t];
            acc += sqrtf(xr * xr + xi * xi);
        }
        float mag = acc * (1.0f / 64.0f);
        smagi[t] = (int)(mag * 1000.0f);
    }
    __syncthreads();
    if (t == 0) {
        int tot = 0;
#pragma unroll
        for (int m = 0; m < MM; m++) tot += smagi[m];
        tot %= NPFR; if (tot < 0) tot += NPFR;
        sIdxFr = tot;
    }
    if (t >= 32 && t < 32 + EDIM) {
        int k = t - 32; float s = 0.f;
        for (int p = 0; p < NIDXC; p++) s += d_esum[(b * NIDXC + p) * EDIM + k];
        sEbar[k] = s * (1.0f / (float)SS);
    }
    __syncthreads();
    // C: fr projection P[c][m]
    {
        float ef[EDIM];
        const float* er = frEmb + (layer * NPFR + sIdxFr) * EDIM;
#pragma unroll
        for (int k = 0; k < EDIM; k++) ef[k] = __ldg(er + k);
        for (int o = t; o < HIDC * MM; o += 256) {
            float v = frB[layer * HIDC * MM + o];
#pragma unroll
            for (int k = 0; k < EDIM; k++)
                v = fmaf(ef[k], frW[(layer * EDIM + k) * HIDC * MM + o], v);
            sP[o >> 4][o & 15] = v;
        }
    }
    // D: complex head mixing O = X W  (W[L][H][i][o][m])
    for (int q = t; q < HIDC * MM; q += 256) {
        int hh = q >> 8;
        int o = (q >> 4) & 15;
        int m = q & 15;
        float ar = 0.f, ai = 0.f;
        const float* wr = Wr + (((size_t)(layer * NHEADS + hh) * CHPH) * CHPH + o) * MM + m;
        const float* wi = Wi + (((size_t)(layer * NHEADS + hh) * CHPH) * CHPH + o) * MM + m;
#pragma unroll
        for (int i = 0; i < CHPH; i++) {
            float xr = sXr[hh * CHPH + i][m], xi = sXi[hh * CHPH + i][m];
            float wrv = wr[i * CHPH * MM], wiv = wi[i * CHPH * MM];
            ar = fmaf(xr, wrv, ar); ar = fmaf(-xi, wiv, ar);
            ai = fmaf(xr, wiv, ai); ai = fmaf(xi, wrv, ai);
        }
        sOr[hh * CHPH + o][m] = ar;
        sOi[hh * CHPH + o][m] = ai;
    }
    __syncthreads();
    // E: gating (analytic branch means)
    if (t < 3 * HIDC) {
        float v;
        if (t < HIDC) {
            v = spB[layer * HIDC + t];
#pragma unroll
            for (int k = 0; k < EDIM; k++)
                v = fmaf(sEbar[k], spW[(layer * EDIM + k) * HIDC + t], v);
        } else if (t < 2 * HIDC) {
            v = sOr[t - HIDC][0] * (1.0f / (float)SS);
        } else {
            v = sP[t - 2 * HIDC][0] * (1.0f / (float)SS);
        }
        sg[t] = v;
    }
    __syncthreads();
    if (t < HIDC) {
        float v = gB1[layer * 64 + t];
        for (int k = 0; k < 3 * HIDC; k++)
            v = fmaf(sg[k], gW1[(layer * 3 * HIDC + k) * 64 + t], v);
        sh1[t] = fmaxf(v, 0.f);
    }
    __syncthreads();
    if (t < 3) {
        float v = gB2[layer * 3 + t];
        for (int k = 0; k < HIDC; k++)
            v = fmaf(sh1[k], gW2[(layer * HIDC + k) * 3 + t], v);
        swv[t] = v;
    }
    __syncthreads();
    if (t == 0) {
        float mx = fmaxf(swv[0], fmaxf(swv[1], swv[2]));
        float e0 = expf(swv[0] - mx), e1 = expf(swv[1] - mx), e2 = expf(swv[2] - mx);
        float inv = 1.f / (e0 + e1 + e2);
        swv[0] = e0 * inv; swv[1] = e1 * inv; swv[2] = e2 * inv;
    }
    __syncthreads();
    // F: gate-folded synthesis coefficients
    if (t < HIDC) {
        int d = t;
        float w0 = swv[0], w1 = swv[1], w2 = swv[2];
        const float invS = 1.0f / (float)SS;
        float* A = d_cA + (b * HIDC + d) * MM;
        float* Bc = d_cB + (b * HIDC + d) * MM;
        A[0] = invS * (w1 * sOr[d][0] + w2 * sP[d][0]);
        Bc[0] = 0.f;
#pragma unroll
        for (int m = 1; m < MM; m++) {
            A[m] = 2.f * invS * (w1 * sOr[d][m] + w2 * sP[d][m]);
            Bc[m] = -2.f * invS * w1 * sOi[d][m];
        }
#pragma unroll
        for (int k = 0; k < EDIM; k++)
            d_spw2[(b * HIDC + d) * EDIM + k] = w0 * spW[(layer * EDIM + k) * HIDC + d];
        d_spb2[b * HIDC + d] = w0 * spB[layer * HIDC + d];
    }
}

// ---------------- per-layer spatial+DC table: T[b][p][d] = spb2 + A0 + emb[p]@spw2 ----
__global__ __launch_bounds__(256) void k_spt(const float* __restrict__ spEmb) {
    int b = blockIdx.x;
    int t = threadIdx.x;
    int d = t & 63, pl = t >> 6;
    int p = blockIdx.y * 4 + pl;
    float v = d_spb2[b * HIDC + d] + d_cA[(b * HIDC + d) * MM];
#pragma unroll
    for (int k = 0; k < EDIM; k++)
        v = fmaf(__ldg(spEmb + p * EDIM + k), d_spw2[(b * HIDC + d) * EDIM + k], v);
    d_spT[(b * NPSP + p) * HIDC + d] = v;
}

// ---------------- fused synthesis + GELU: warp = quartet q, lanes = channels ------
// Coalesced Tb gathers (lanes read consecutive d of the same row), warp-uniform
// trig recurrence, smem tile staging for coalesced h writeback.
__global__ __launch_bounds__(256) void k_fusion(int last,
        const float* __restrict__ pW, const float* __restrict__ pB,
        float* __restrict__ out) {
    __shared__ float sA[HIDC][MM + 1];
    __shared__ float sB[HIDC][MM + 1];
    __shared__ float sgm[32][HIDC + 1];   // [slot = w*4+j][d]
    __shared__ float sPJ[HIDC];
    int b = blockIdx.x, tile = blockIdx.y, t = threadIdx.x;
    int w = t >> 5, lane = t & 31;
    for (int i = t; i < HIDC * MM; i += 256) {
        sA[i >> 4][i & 15] = d_cA[b * HIDC * MM + i];
        sB[i >> 4][i & 15] = d_cB[b * HIDC * MM + i];
    }
    if (t < HIDC) sPJ[t] = last ? pW[t] : 0.f;
    __syncthreads();

    int q = tile * 8 + w;
    const float* Tb = d_spT + b * NPSP * HIDC;
    const int* ib = d_idx + b * SS;
    if (q != 0) {
        int i0 = ib[q] * HIDC;
        int i1 = ib[8192 - q] * HIDC;
        int i2 = ib[8192 + q] * HIDC;
        int i3 = ib[16384 - q] * HIDC;
        float c1 = __ldg(&d_tabC[q]), s1 = __ldg(&d_tabS[q]);
        float cosv[MM], sinv[MM];
        cosv[0] = 1.f; sinv[0] = 0.f; cosv[1] = c1; sinv[1] = s1;
        float t2 = c1 + c1;
#pragma unroll
        for (int m = 2; m < MM; m++) {
            cosv[m] = fmaf(t2, cosv[m - 1], -cosv[m - 2]);
            sinv[m] = fmaf(t2, sinv[m - 1], -sinv[m - 2]);
        }
#pragma unroll
        for (int half = 0; half < 2; half++) {
            int d = lane + 32 * half;
            float Ue = 0.f, Uo = 0.f, We = 0.f, Wo = 0.f;
#pragma unroll
            for (int m = 1; m < MM; m++) {
                float a = sA[d][m], bb = sB[d][m];
                if (m & 1) { Uo = fmaf(a, cosv[m], Uo); Wo = fmaf(bb, sinv[m], Wo); }
                else       { Ue = fmaf(a, cosv[m], Ue); We = fmaf(bb, sinv[m], We); }
            }
            float up = Ue + Uo, um = Ue - Uo, wp = We + Wo, wm = We - Wo;
            sgm[w * 4 + 0][d] = gelu_exact(Tb[i0 + d] + up + wp);
            sgm[w * 4 + 1][d] = gelu_exact(Tb[i1 + d] + um - wm);
            sgm[w * 4 + 2][d] = gelu_exact(Tb[i2 + d] + um + wm);
            sgm[w * 4 + 3][d] = gelu_exact(Tb[i3 + d] + up - wp);
        }
    } else {
        // tile 0, warp 0: special positions {0, 4096, 8192, 12288} -> slots 0..3
        int i0 = ib[0] * HIDC;
        int i1 = ib[4096] * HIDC;
        int i2 = ib[8192] * HIDC;
        int i3 = ib[12288] * HIDC;
#pragma unroll
        for (int half = 0; half < 2; half++) {
            int d = lane + 32 * half;
            float v0 = Tb[i0 + d], v1 = Tb[i1 + d], v2 = Tb[i2 + d], v3 = Tb[i3 + d];
#pragma unroll
            for (int m = 1; m < MM; m++) {
                float a = sA[d][m], bb = sB[d][m];
                v0 += a;
                v2 += (m & 1) ? -a : a;
                int mm = m & 3;
                if (mm == 0)      { v1 += a;  v3 += a; }
                else if (mm == 2) { v1 -= a;  v3 -= a; }
                else if (mm == 1) { v1 += bb; v3 -= bb; }
                else              { v1 -= bb; v3 += bb; }
            }
            sgm[0][d] = gelu_exact(v0);
            sgm[1][d] = gelu_exact(v1);
            sgm[2][d] = gelu_exact(v2);
            sgm[3][d] = gelu_exact(v3);
        }
    }
    __syncthreads();

    if (!last) {
        // h writeback: warp handles rows d = w + 8*it; lanes = (j, wq): 8-runs of s
        int j = lane >> 3, wq = lane & 7;
#pragma unroll
        for (int it = 0; it < 8; it++) {
            int d = w + 8 * it;
            float g = sgm[wq * 4 + j][d];
            int s;
            if (tile == 0 && wq == 0) {
                s = (j == 0) ? 0 : (j == 1) ? 4096 : (j == 2) ? 8192 : 12288;
            } else {
                int q2 = tile * 8 + wq;
                s = (j == 0) ? q2 : (j == 1) ? 8192 - q2 : (j == 2) ? 8192 + q2 : 16384 - q2;
            }
            d_h[(size_t)(b * HIDC + d) * SS + s] = g;
        }
    }
    if (t < 32) {
        int slot = t;
        int jj = slot & 3, wq = slot >> 2;
        int pos;
        if (tile == 0 && wq == 0) {
            pos = (jj == 0) ? 0 : (jj == 1) ? 4096 : (jj == 2) ? 8192 : 12288;
        } else {
            int q2 = tile * 8 + wq;
            pos = (jj == 0) ? q2 : (jj == 1) ? 8192 - q2 : (jj == 2) ? 8192 + q2 : 16384 - q2;
        }
        float tot = 0.f;
        if (last) {
#pragma unroll 16
            for (int d = 0; d < HIDC; d++) tot = fmaf(sPJ[d], sgm[slot][d], tot);
            out[b * SS + pos] = tot + pB[0];
        } else {
#pragma unroll 16
            for (int d = 0; d < HIDC; d++) tot += sgm[slot][d];
            d_sC[b * SS + pos] = tot;
        }
    }
}

extern "C" void kernel_launch(void* const* d_in, const int* in_sizes, int n_in,
                              void* d_out, int out_size) {
    const float* x     = (const float*)d_in[0];
    const float* liftW = (const float*)d_in[1];
    const float* liftB = (const float*)d_in[2];
    const float* projW = (const float*)d_in[3];
    const float* projB = (const float*)d_in[4];
    const float* spEmb = (const float*)d_in[5];
    const float* spW   = (const float*)d_in[6];
    const float* spB   = (const float*)d_in[7];
    const float* frEmb = (const float*)d_in[8];
    const float* frW   = (const float*)d_in[9];
    const float* frB   = (const float*)d_in[10];
    const float* gW1   = (const float*)d_in[11];
    const float* gB1   = (const float*)d_in[12];
    const float* gW2   = (const float*)d_in[13];
    const float* gB2   = (const float*)d_in[14];
    const float* mhWr  = (const float*)d_in[15];
    const float* mhWi  = (const float*)d_in[16];

    k_table<<<SS / 256, 256>>>();
    k_lift<<<dim3(BB, SS / 256), 256>>>(x, liftW, liftB);
    for (int l = 0; l < LL; l++) {
        k_idx<<<dim3(BB, NIDXC), 256>>>(spEmb + l * NPSP * EDIM);
        k_dft<<<dim3(BB * 32, NCHUNK * 2), 256>>>();
        k_coeff<<<BB, 256>>>(l, frEmb, frW, frB, spW, spB,
                             gW1, gB1, gW2, gB2, mhWr, mhWi);
        k_spt<<<dim3(BB, NPSP / 4), 256>>>(spEmb + l * NPSP * EDIM);
        k_fusion<<<dim3(BB, QQ / 8), 256>>>((l == LL - 1) ? 1 : 0,
                                            projW, projB, (float*)d_out);
    }
}

// round 14
// speedup vs baseline: 1.7304x; 1.6791x over previous
#include <cuda_runtime.h>
#include <math.h>

#define BB 16
#define CIN 3
#define HIDC 64
#define SS 16384
#define QQ 4096               // SS/4
#define MM 16
#define LL 4
#define NPSP 500
#define NPFR 200
#define EDIM 8
#define NHEADS 4
#define CHPH 16               // channels per head
#define NCHUNK 4              // DFT q-chunks (layer-0 kernel)
#define NIDXC 8               // idx-kernel chunks
#define NTILE 64              // fusion tiles (64 quartets each) = partials count

// ---------------- scratch (device globals; no allocation) ----------------
__device__ float d_tabC[SS];
__device__ float d_tabS[SS];
__device__ float d_tabC7[QQ];
__device__ float d_tabS7[QQ];
__device__ float d_tabC8[QQ];
__device__ float d_tabS8[QQ];
__device__ float d_h[BB * HIDC * SS];                    // only layer-0 (lift -> dft)
__device__ float d_sC[BB * SS];                          // channel-sum
__device__ int   d_idx[BB * SS];                         // spatial hash indices
__device__ float d_Xpart[(size_t)BB * HIDC * 128 * 32];  // DFT partials [c][p<128][32]
__device__ float d_esum[BB * NIDXC * EDIM];              // partial emb sums
__device__ float d_cA[BB * HIDC * MM];                   // fused cos coefficients
__device__ float d_cB[BB * HIDC * MM];                   // fused sin coefficients
__device__ float d_spw2[BB * HIDC * EDIM];               // gate-folded spatial W
__device__ float d_spb2[BB * HIDC];                      // gate-folded spatial b
__device__ float d_spT[BB * NPSP * HIDC];                // per-pattern sp+DC table

__device__ __forceinline__ float gelu_exact(float v) {
    return 0.5f * v * (1.0f + erff(v * 0.70710678118654752f));
}

// ---------------- trig tables (exact base angles) ----------------
__global__ void k_table() {
    int i = blockIdx.x * blockDim.x + threadIdx.x;
    if (i < SS) {
        double w = 6.283185307179586476925286766559 / (double)SS;
        double a = w * (double)i;
        d_tabC[i] = (float)cos(a);
        d_tabS[i] = (float)sin(a);
        if (i < QQ) {
            d_tabC7[i] = (float)cos(a * 7.0);
            d_tabS7[i] = (float)sin(a * 7.0);
            d_tabC8[i] = (float)cos(a * 8.0);
            d_tabS8[i] = (float)sin(a * 8.0);
        }
    }
}

// ---------------- lifting: x[B,3,S] -> h[B,64,S], plus channel-sum ----------------
__global__ __launch_bounds__(256) void k_lift(const float* __restrict__ x,
                                              const float* __restrict__ W,
                                              const float* __restrict__ bv) {
    __shared__ float sW[CIN * HIDC];
    __shared__ float sB[HIDC];
    int t = threadIdx.x;
    if (t < CIN * HIDC) sW[t] = W[t];
    if (t < HIDC) sB[t] = bv[t];
    __syncthreads();
    int b = blockIdx.x;
    int s = blockIdx.y * 256 + t;
    float x0 = x[(b * CIN + 0) * SS + s];
    float x1 = x[(b * CIN + 1) * SS + s];
    float x2 = x[(b * CIN + 2) * SS + s];
    float sc = 0.f;
#pragma unroll 8
    for (int d = 0; d < HIDC; d++) {
        float v = sB[d];
        v = fmaf(x0, sW[0 * HIDC + d], v);
        v = fmaf(x1, sW[1 * HIDC + d], v);
        v = fmaf(x2, sW[2 * HIDC + d], v);
        d_h[(b * HIDC + d) * SS + s] = v;
        sc += v;
    }
    d_sC[b * SS + s] = sc;
}

// ---------------- spatial hash indices + embedding mean partials ----------------
__global__ __launch_bounds__(256) void k_idx(const float* __restrict__ spEmb) {
    int b = blockIdx.x;
    int chunk = blockIdx.y;
    int t = threadIdx.x;
    const float* sc = d_sC + b * SS;
    float es[EDIM];
#pragma unroll
    for (int k = 0; k < EDIM; k++) es[k] = 0.f;
    const int span = SS / NIDXC;        // 2048
    for (int it = 0; it < span / 256; it++) {
        int s = chunk * span + it * 256 + t;
        int sm2 = max(s - 2, 0), sm1 = max(s - 1, 0), sp1 = min(s + 1, SS - 1);
        float w = sc[sm2] + sc[sm1] + sc[s] + sc[sp1];
        int iv = (int)(w * 31.0f);      // trunc toward zero
        iv %= NPSP; if (iv < 0) iv += NPSP;
        d_idx[b * SS + s] = iv;
        const float* e = spEmb + iv * EDIM;
#pragma unroll
        for (int k = 0; k < EDIM; k++) es[k] += __ldg(e + k);
    }
    __shared__ float red[256][EDIM];
#pragma unroll
    for (int k = 0; k < EDIM; k++) red[t][k] = es[k];
    __syncthreads();
    for (int off = 128; off > 0; off >>= 1) {
        if (t < off) {
#pragma unroll
            for (int k = 0; k < EDIM; k++) red[t][k] += red[t + off][k];
        }
        __syncthreads();
    }
    if (t < EDIM) d_esum[(b * NIDXC + chunk) * EDIM + t] = red[0][t];
}

// ---------------- layer-0 DFT: quartet fold + mode-split (8 modes/block) ---------
// Writes partials [c][part=chunk*8+w <32][32: m*2+ri], m = half*8+lm.
__global__ __launch_bounds__(256) void k_dft() {
    int bc = blockIdx.x;            // b*32 + channel-pair
    int b = bc >> 5, cp = bc & 31;
    int cy = blockIdx.y;            // chunk*2 + half
    int chunk = cy >> 1, half = cy & 1;
    const float* h0 = d_h + (size_t)(b * HIDC + cp * 2) * SS;
    const float* h1 = h0 + SS;
    int t = threadIdx.x;
    float aR0[8], aI0[8], aR1[8], aI1[8];
#pragma unroll
    for (int lm = 0; lm < 8; lm++) { aR0[lm] = 0.f; aI0[lm] = 0.f; aR1[lm] = 0.f; aI1[lm] = 0.f; }
#pragma unroll
    for (int it = 0; it < QQ / NCHUNK / 256; it++) {     // 4 iterations
        int q = chunk * (QQ / NCHUNK) + it * 256 + t;
        if (q == 0) {
            float u0 = h0[0], u1 = h1[0];
            float v0 = h0[8192], v1 = h1[8192];
            float w0 = h0[4096], w1 = h1[4096];
            float z0 = h0[12288], z1 = h1[12288];
            float wzp0 = w0 + z0, wzm0 = w0 - z0;
            float wzp1 = w1 + z1, wzm1 = w1 - z1;
#pragma unroll
            for (int lm = 0; lm < 8; lm++) {
                int m = half * 8 + lm;
                aR0[lm] += u0 + ((m & 1) ? -v0 : v0);
                aR1[lm] += u1 + ((m & 1) ? -v1 : v1);
                int mm = m & 3;
                if (mm == 0)      { aR0[lm] += wzp0; aR1[lm] += wzp1; }
                else if (mm == 2) { aR0[lm] -= wzp0; aR1[lm] -= wzp1; }
                else if (mm == 1) { aI0[lm] += wzm0; aI1[lm] += wzm1; }
                else              { aI0[lm] -= wzm0; aI1[lm] -= wzm1; }
            }
            continue;
        }
        float a0 = h0[q], b0v = h0[8192 - q], c0v = h0[8192 + q], e0 = h0[16384 - q];
        float a1 = h1[q], b1v = h1[8192 - q], c1v = h1[8192 + q], e1 = h1[16384 - q];
        float p0 = a0 + e0, q0v = b0v + c0v, r0 = a0 - e0, t0v = c0v - b0v;
        float xe0 = p0 + q0v, xo0 = p0 - q0v, ye0 = r0 + t0v, yo0 = r0 - t0v;
        float p1 = a1 + e1, q1v = b1v + c1v, r1 = a1 - e1, t1v = c1v - b1v;
        float xe1 = p1 + q1v, xo1 = p1 - q1v, ye1 = r1 + t1v, yo1 = r1 - t1v;
        float cb = __ldg(&d_tabC[q]);
        float t2 = cb + cb;
        float cc, sv, cm1, sm1;
        if (half == 0) {
            cc = 1.f; sv = 0.f;
            cm1 = cb; sm1 = -__ldg(&d_tabS[q]);
        } else {
            cc  = __ldg(&d_tabC8[q]); sv  = __ldg(&d_tabS8[q]);
            cm1 = __ldg(&d_tabC7[q]); sm1 = __ldg(&d_tabS7[q]);
        }
#pragma unroll
        for (int lm = 0; lm < 8; lm++) {
            if (lm & 1) {
                aR0[lm] = fmaf(cc, xo0, aR0[lm]); aI0[lm] = fmaf(sv, yo0, aI0[lm]);
                aR1[lm] = fmaf(cc, xo1, aR1[lm]); aI1[lm] = fmaf(sv, yo1, aI1[lm]);
            } else {
                aR0[lm] = fmaf(cc, xe0, aR0[lm]); aI0[lm] = fmaf(sv, ye0, aI0[lm]);
                aR1[lm] = fmaf(cc, xe1, aR1[lm]); aI1[lm] = fmaf(sv, ye1, aI1[lm]);
            }
            float cn = fmaf(t2, cc, -cm1);
            float sn = fmaf(t2, sv, -sm1);
            cm1 = cc; cc = cn; sm1 = sv; sv = sn;
        }
    }
#pragma unroll
    for (int off = 16; off > 0; off >>= 1) {
#pragma unroll
        for (int lm = 0; lm < 8; lm++) {
            aR0[lm] += __shfl_down_sync(0xffffffffu, aR0[lm], off);
            aI0[lm] += __shfl_down_sync(0xffffffffu, aI0[lm], off);
            aR1[lm] += __shfl_down_sync(0xffffffffu, aR1[lm], off);
            aI1[lm] += __shfl_down_sync(0xffffffffu, aI1[lm], off);
        }
    }
    int w = t >> 5, lane = t & 31;
    if (lane == 0) {
        int part = chunk * 8 + w;                      // 0..31
        float* o0 = d_Xpart + ((size_t)(b * HIDC + cp * 2) * 128 + part) * 32;
        float* o1 = o0 + (size_t)128 * 32;
#pragma unroll
        for (int lm = 0; lm < 8; lm++) {
            int m = half * 8 + lm;
            o0[2 * m] = aR0[lm]; o0[2 * m + 1] = aI0[lm];
            o1[2 * m] = aR1[lm]; o1[2 * m + 1] = aI1[lm];
        }
    }
}

// ---------------- per-batch: reduce X, mh mixing, fr hash, gating, coefficients ----------------
__global__ __launch_bounds__(256) void k_coeff(int layer, int NP,
        const float* __restrict__ frEmb, const float* __restrict__ frW, const float* __restrict__ frB,
        const float* __restrict__ spW, const float* __restrict__ spB,
        const float* __restrict__ gW1, const float* __restrict__ gB1,
        const float* __restrict__ gW2, const float* __restrict__ gB2,
        const float* __restrict__ Wr, const float* __restrict__ Wi) {
    int b = blockIdx.x, t = threadIdx.x;
    __shared__ float sXr[HIDC][MM], sXi[HIDC][MM];
    __shared__ float sOr[HIDC][MM], sOi[HIDC][MM];
    __shared__ float sP[HIDC][MM];
    __shared__ int   smagi[MM];
    __shared__ int   sIdxFr;
    __shared__ float sEbar[EDIM];
    __shared__ float sg[3 * HIDC];
    __shared__ float sh1[HIDC];
    __shared__ float swv[3];

    // A: reduce DFT partials (fixed ascending order), negate imag to true sign
    for (int jg = t; jg < HIDC * 32; jg += 256) {
        int c = jg >> 5, j = jg & 31;
        const float* p = d_Xpart + ((size_t)(b * HIDC + c) * 128) * 32 + j;
        float s = 0.f;
        for (int q = 0; q < NP; q++) s += p[q * 32];
        int m = j >> 1;
        if (j & 1) sXi[c][m] = -s; else sXr[c][m] = s;
    }
    __syncthreads();
    // B: spectral hash
    if (t < MM) {
        float acc = 0.f;
        for (int c = 0; c < HIDC; c++) {
            float xr = sXr[c][t], xi = sXi[c][t];
            acc += sqrtf(xr * xr + xi * xi);
        }
        float mag = acc * (1.0f / 64.0f);
        smagi[t] = (int)(mag * 1000.0f);
    }
    __syncthreads();
    if (t == 0) {
        int tot = 0;
#pragma unroll
        for (int m = 0; m < MM; m++) tot += smagi[m];
        tot %= NPFR; if (tot < 0) tot += NPFR;
        sIdxFr = tot;
    }
    if (t >= 32 && t < 32 + EDIM) {
        int k = t - 32; float s = 0.f;
        for (int p = 0; p < NIDXC; p++) s += d_esum[(b * NIDXC + p) * EDIM + k];
        sEbar[k] = s * (1.0f / (float)SS);
    }
    __syncthreads();
    // C: fr projection P[c][m]
    {
        float ef[EDIM];
        const float* er = frEmb + (layer * NPFR + sIdxFr) * EDIM;
#pragma unroll
        for (int k = 0; k < EDIM; k++) ef[k] = __ldg(er + k);
        for (int o = t; o < HIDC * MM; o += 256) {
            float v = frB[layer * HIDC * MM + o];
#pragma unroll
            for (int k = 0; k < EDIM; k++)
                v = fmaf(ef[k], frW[(layer * EDIM + k) * HIDC * MM + o], v);
            sP[o >> 4][o & 15] = v;
        }
    }
    // D: complex head mixing O = X W  (W[L][H][i][o][m])
    for (int q = t; q < HIDC * MM; q += 256) {
        int hh = q >> 8;
        int o = (q >> 4) & 15;
        int m = q & 15;
        float ar = 0.f, ai = 0.f;
        const float* wr = Wr + (((size_t)(layer * NHEADS + hh) * CHPH) * CHPH + o) * MM + m;
        const float* wi = Wi + (((size_t)(layer * NHEADS + hh) * CHPH) * CHPH + o) * MM + m;
#pragma unroll
        for (int i = 0; i < CHPH; i++) {
            float xr = sXr[hh * CHPH + i][m], xi = sXi[hh * CHPH + i][m];
            float wrv = wr[i * CHPH * MM], wiv = wi[i * CHPH * MM];
            ar = fmaf(xr, wrv, ar); ar = fmaf(-xi, wiv, ar);
            ai = fmaf(xr, wiv, ai); ai = fmaf(xi, wrv, ai);
        }
        sOr[hh * CHPH + o][m] = ar;
        sOi[hh * CHPH + o][m] = ai;
    }
    __syncthreads();
    // E: gating (analytic branch means)
    if (t < 3 * HIDC) {
        float v;
        if (t < HIDC) {
            v = spB[layer * HIDC + t];
#pragma unroll
            for (int k = 0; k < EDIM; k++)
                v = fmaf(sEbar[k], spW[(layer * EDIM + k) * HIDC + t], v);
        } else if (t < 2 * HIDC) {
            v = sOr[t - HIDC][0] * (1.0f / (float)SS);
        } else {
            v = sP[t - 2 * HIDC][0] * (1.0f / (float)SS);
        }
        sg[t] = v;
    }
    __syncthreads();
    if (t < HIDC) {
        float v = gB1[layer * 64 + t];
        for (int k = 0; k < 3 * HIDC; k++)
            v = fmaf(sg[k], gW1[(layer * 3 * HIDC + k) * 64 + t], v);
        sh1[t] = fmaxf(v, 0.f);
    }
    __syncthreads();
    if (t < 3) {
        float v = gB2[layer * 3 + t];
        for (int k = 0; k < HIDC; k++)
            v = fmaf(sh1[k], gW2[(layer * HIDC + k) * 3 + t], v);
        swv[t] = v;
    }
    __syncthreads();
    if (t == 0) {
        float mx = fmaxf(swv[0], fmaxf(swv[1], swv[2]));
        float e0 = expf(swv[0] - mx), e1 = expf(swv[1] - mx), e2 = expf(swv[2] - mx);
        float inv = 1.f / (e0 + e1 + e2);
        swv[0] = e0 * inv; swv[1] = e1 * inv; swv[2] = e2 * inv;
    }
    __syncthreads();
    // F: gate-folded synthesis coefficients
    if (t < HIDC) {
        int d = t;
        float w0 = swv[0], w1 = swv[1], w2 = swv[2];
        const float invS = 1.0f / (float)SS;
        float* A = d_cA + (b * HIDC + d) * MM;
        float* Bc = d_cB + (b * HIDC + d) * MM;
        A[0] = invS * (w1 * sOr[d][0] + w2 * sP[d][0]);
        Bc[0] = 0.f;
#pragma unroll
        for (int m = 1; m < MM; m++) {
            A[m] = 2.f * invS * (w1 * sOr[d][m] + w2 * sP[d][m]);
            Bc[m] = -2.f * invS * w1 * sOi[d][m];
        }
#pragma unroll
        for (int k = 0; k < EDIM; k++)
            d_spw2[(b * HIDC + d) * EDIM + k] = w0 * spW[(layer * EDIM + k) * HIDC + d];
        d_spb2[b * HIDC + d] = w0 * spB[layer * HIDC + d];
    }
}

// ---------------- per-layer spatial+DC table: T[b][p][d] = spb2 + A0 + emb[p]@spw2 ----
__global__ __launch_bounds__(256) void k_spt(const float* __restrict__ spEmb) {
    int b = blockIdx.x;
    int t = threadIdx.x;
    int d = t & 63, pl = t >> 6;
    int p = blockIdx.y * 4 + pl;
    float v = d_spb2[b * HIDC + d] + d_cA[(b * HIDC + d) * MM];
#pragma unroll
    for (int k = 0; k < EDIM; k++)
        v = fmaf(__ldg(spEmb + p * EDIM + k), d_spw2[(b * HIDC + d) * EDIM + k], v);
    d_spT[(b * NPSP + p) * HIDC + d] = v;
}

// ---------------- fused synthesis + GELU + NEXT-LAYER DFT partials ----------------
// warp = quartet; lanes = 32 channels x 2 halves. 8 quartets per warp, 64 per block.
// !last: accumulate 16-mode DFT partials of g (reusing cosv/sinv), write [c][tile][32],
//        write sC. No h traffic at all.  last: output projection only.
__global__ __launch_bounds__(256, 2) void k_fusion(int last,
        const float* __restrict__ pW, const float* __restrict__ pB,
        float* __restrict__ out) {
    __shared__ float sA[HIDC][MM + 1];
    __shared__ float sB[HIDC][MM + 1];
    __shared__ float red[HIDC][33];
    __shared__ float sPJ[HIDC];
    int b = blockIdx.x, tile = blockIdx.y, t = threadIdx.x;
    int w = t >> 5, lane = t & 31;
    for (int i = t; i < HIDC * MM; i += 256) {
        sA[i >> 4][i & 15] = d_cA[b * HIDC * MM + i];
        sB[i >> 4][i & 15] = d_cB[b * HIDC * MM + i];
    }
    if (t < HIDC) sPJ[t] = last ? pW[t] : 0.f;
    if (!last) for (int i = t; i < HIDC * 33; i += 256) (&red[0][0])[i] = 0.f;
    __syncthreads();

    float accR[2][MM], accI[2][MM];
    if (!last) {
#pragma unroll
        for (int hf = 0; hf < 2; hf++)
#pragma unroll
            for (int m = 0; m < MM; m++) { accR[hf][m] = 0.f; accI[hf][m] = 0.f; }
    }
    const float* Tb = d_spT + b * NPSP * HIDC;
    const int* ib = d_idx + b * SS;
    float pj[2]; pj[0] = sPJ[lane]; pj[1] = sPJ[lane + 32];

    for (int k = 0; k < 8; k++) {
        int q = tile * 64 + w * 8 + k;
        float sj[4] = {0.f, 0.f, 0.f, 0.f};
        if (q != 0) {
            int i0 = ib[q] * HIDC;
            int i1 = ib[8192 - q] * HIDC;
            int i2 = ib[8192 + q] * HIDC;
            int i3 = ib[16384 - q] * HIDC;
            float c1 = __ldg(&d_tabC[q]), s1 = __ldg(&d_tabS[q]);
            float cosv[MM], sinv[MM];
            cosv[0] = 1.f; sinv[0] = 0.f; cosv[1] = c1; sinv[1] = s1;
            float t2 = c1 + c1;
#pragma unroll
            for (int m = 2; m < MM; m++) {
                cosv[m] = fmaf(t2, cosv[m - 1], -cosv[m - 2]);
                sinv[m] = fmaf(t2, sinv[m - 1], -sinv[m - 2]);
            }
#pragma unroll
            for (int hf = 0; hf < 2; hf++) {
                int d = lane + 32 * hf;
                float Ue = 0.f, Uo = 0.f, We = 0.f, Wo = 0.f;
#pragma unroll
                for (int m = 1; m < MM; m++) {
                    float a = sA[d][m], bb = sB[d][m];
                    if (m & 1) { Uo = fmaf(a, cosv[m], Uo); Wo = fmaf(bb, sinv[m], Wo); }
                    else       { Ue = fmaf(a, cosv[m], Ue); We = fmaf(bb, sinv[m], We); }
                }
                float up = Ue + Uo, um = Ue - Uo, wp = We + Wo, wm = We - Wo;
                float g0 = gelu_exact(Tb[i0 + d] + up + wp);
                float g1 = gelu_exact(Tb[i1 + d] + um - wm);
                float g2 = gelu_exact(Tb[i2 + d] + um + wm);
                float g3 = gelu_exact(Tb[i3 + d] + up - wp);
                if (last) {
                    sj[0] = fmaf(pj[hf], g0, sj[0]); sj[1] = fmaf(pj[hf], g1, sj[1]);
                    sj[2] = fmaf(pj[hf], g2, sj[2]); sj[3] = fmaf(pj[hf], g3, sj[3]);
                } else {
                    sj[0] += g0; sj[1] += g1; sj[2] += g2; sj[3] += g3;
                    // DFT fold: a=g(q), b=g(S/2-q), c=g(S/2+q), e=g(S-q)
                    float p_ = g0 + g3, qv = g1 + g2, r_ = g0 - g3, tv = g2 - g1;
                    float xe = p_ + qv, xo = p_ - qv, ye = r_ + tv, yo = r_ - tv;
                    accR[hf][0] += xe;
#pragma unroll
                    for (int m = 1; m < MM; m++) {
                        if (m & 1) {
                            accR[hf][m] = fmaf(cosv[m], xo, accR[hf][m]);
                            accI[hf][m] = fmaf(sinv[m], yo, accI[hf][m]);
                        } else {
                            accR[hf][m] = fmaf(cosv[m], xe, accR[hf][m]);
                            accI[hf][m] = fmaf(sinv[m], ye, accI[hf][m]);
                        }
                    }
                }
            }
        } else {
            // special positions {0, 4096, 8192, 12288}, exact trig
            int i0 = ib[0] * HIDC, i1 = ib[4096] * HIDC;
            int i2 = ib[8192] * HIDC, i3 = ib[12288] * HIDC;
#pragma unroll
            for (int hf = 0; hf < 2; hf++) {
                int d = lane + 32 * hf;
                float v0 = Tb[i0 + d], v1 = Tb[i1 + d], v2 = Tb[i2 + d], v3 = Tb[i3 + d];
#pragma unroll
                for (int m = 1; m < MM; m++) {
                    float a = sA[d][m], bb = sB[d][m];
                    v0 += a;
                    v2 += (m & 1) ? -a : a;
                    int mm = m & 3;
                    if (mm == 0)      { v1 += a;  v3 += a; }
                    else if (mm == 2) { v1 -= a;  v3 -= a; }
                    else if (mm == 1) { v1 += bb; v3 -= bb; }
                    else              { v1 -= bb; v3 += bb; }
                }
                float g0 = gelu_exact(v0), g1 = gelu_exact(v1);
                float g2 = gelu_exact(v2), g3 = gelu_exact(v3);
                if (last) {
                    sj[0] = fmaf(pj[hf], g0, sj[0]); sj[1] = fmaf(pj[hf], g1, sj[1]);
                    sj[2] = fmaf(pj[hf], g2, sj[2]); sj[3] = fmaf(pj[hf], g3, sj[3]);
                } else {
                    sj[0] += g0; sj[1] += g1; sj[2] += g2; sj[3] += g3;
                    // special fold: u=g0(s=0), w=g1(4096), v=g2(8192), z=g3(12288)
                    float wzp = g1 + g3, wzm = g1 - g3;
#pragma unroll
                    for (int m = 0; m < MM; m++) {
                        accR[hf][m] += g0 + ((m & 1) ? -g2 : g2);
                        int mm = m & 3;
                        if (mm == 0)      accR[hf][m] += wzp;
                        else if (mm == 2) accR[hf][m] -= wzp;
                        else if (mm == 1) accI[hf][m] += wzm;
                        else              accI[hf][m] -= wzm;
                    }
                }
            }
        }
        // warp reduce sj over 64 channels, lane 0 writes
#pragma unroll
        for (int j = 0; j < 4; j++) {
            float v = sj[j];
#pragma unroll
            for (int off = 16; off > 0; off >>= 1)
                v += __shfl_down_sync(0xffffffffu, v, off);
            if (lane == 0) {
                int pos;
                if (q != 0) pos = (j == 0) ? q : (j == 1) ? 8192 - q : (j == 2) ? 8192 + q : 16384 - q;
                else        pos = (j == 0) ? 0 : (j == 1) ? 4096 : (j == 2) ? 8192 : 12288;
                if (last) out[b * SS + pos] = v + pB[0];
                else d_sC[b * SS + pos] = v;
            }
        }
    }
    if (!last) {
        // fixed-order cross-warp accumulation (w ascending) -> deterministic
        for (int ww = 0; ww < 8; ww++) {
            if (w == ww) {
#pragma unroll
                for (int hf = 0; hf < 2; hf++) {
                    int d = lane + 32 * hf;
#pragma unroll
                    for (int m = 0; m < MM; m++) {
                        red[d][2 * m] += accR[hf][m];
                        red[d][2 * m + 1] += accI[hf][m];
                    }
                }
            }
            __syncthreads();
        }
        for (int i = t; i < HIDC * 32; i += 256) {
            int d = i >> 5, j = i & 31;
            d_Xpart[((size_t)(b * HIDC + d) * 128 + tile) * 32 + j] = red[d][j];
        }
    }
}

extern "C" void kernel_launch(void* const* d_in, const int* in_sizes, int n_in,
                              void* d_out, int out_size) {
    const float* x     = (const float*)d_in[0];
    const float* liftW = (const float*)d_in[1];
    const float* liftB = (const float*)d_in[2];
    const float* projW = (const float*)d_in[3];
    const float* projB = (const float*)d_in[4];
    const float* spEmb = (const float*)d_in[5];
    const float* spW   = (const float*)d_in[6];
    const float* spB   = (const float*)d_in[7];
    const float* frEmb = (const float*)d_in[8];
    const float* frW   = (const float*)d_in[9];
    const float* frB   = (const float*)d_in[10];
    const float* gW1   = (const float*)d_in[11];
    const float* gB1   = (const float*)d_in[12];
    const float* gW2   = (const float*)d_in[13];
    const float* gB2   = (const float*)d_in[14];
    const float* mhWr  = (const float*)d_in[15];
    const float* mhWi  = (const float*)d_in[16];

    k_table<<<SS / 256, 256>>>();
    k_lift<<<dim3(BB, SS / 256), 256>>>(x, liftW, liftB);
    for (int l = 0; l < LL; l++) {
        k_idx<<<dim3(BB, NIDXC), 256>>>(spEmb + l * NPSP * EDIM);
        if (l == 0) k_dft<<<dim3(BB * 32, NCHUNK * 2), 256>>>();
        k_coeff<<<BB, 256>>>(l, (l == 0) ? 32 : NTILE,
                             frEmb, frW, frB, spW, spB,
                             gW1, gB1, gW2, gB2, mhWr, mhWi);
        k_spt<<<dim3(BB, NPSP / 4), 256>>>(spEmb + l * NPSP * EDIM);
        k_fusion<<<dim3(BB, NTILE), 256>>>((l == LL - 1) ? 1 : 0,
                                           projW, projB, (float*)d_out);
    }
}